// round 9
// baseline (speedup 1.0000x reference)
#include <cuda_runtime.h>
#include <cstdint>

// LIF spiking layer: h = x @ W^T + b  (M=32768, N=512, K=512), then
// sequential LIF scan over T=256: v = 0.5v + h_t; s = (v>=1); hard reset.
//
// CONSTRAINT (established R4/R5/R7): the checker demands h match the
// reference's sequential-k fp32 FMA chain to ~5e-7 — i.e. order-exact fp32.
// Any tensor-core tree reduction flips ~24 spikes -> rel_err 2.7e-3 > 1e-3.
// So: SIMT fp32 GEMM with sequential-k accumulation (proven rel_err 0.0),
// packed fma.rn.f32x2 for issue-slot relief. This sits at the fp32 FMA-pipe
// roofline (~481us). Scan optimized: 2 neurons/thread (float2), 64-thread
// blocks for wave balance.

#define M_TOT 32768
#define N_TOT 512
#define K_TOT 512
#define T_STEPS 256
#define BH 65536
#define BH2 32768   // float2 pairs per timestep plane

#define BM 128
#define BN 128
#define BK 16
#define NCHUNK (K_TOT / BK)   // 32

__device__ float g_h[M_TOT * N_TOT];   // 64 MB scratch for h

typedef unsigned long long ull;

__device__ __forceinline__ void ffma2(ull& d, ull a, ull b) {
    // d.lo += a.lo*b.lo ; d.hi += a.hi*b.hi  (two independent rn fp32 FMAs)
    asm("fma.rn.f32x2 %0, %1, %2, %0;" : "+l"(d) : "l"(a), "l"(b));
}

// ---------------------------------------------------------------------------
// GEMM: C = A @ B^T + bias -> g_h   (identical to the round-3 passing kernel)
// A = x (32768 x 512, K contiguous), B = W (512 x 512, K contiguous).
// 256 threads, 128x128 CTA tile, 8x8 per-thread tile. Sequential-k fp32 FMA
// per output element (matches reference rounding exactly -> rel_err 0.0).
// As stored DUPLICATED so the FFMA2 broadcast operand is one LDS.64.
// ---------------------------------------------------------------------------
#define ASTRIDE (2 * BM + 8)   // 264
#define BSTRIDE (BN + 4)       // 132

__global__ __launch_bounds__(256, 2)
void gemm_bias_kernel(const float* __restrict__ A,
                      const float* __restrict__ Bw,
                      const float* __restrict__ bias) {
    __shared__ float As[BK][ASTRIDE];
    __shared__ float Bs[BK][BSTRIDE];

    const int tid = (int)threadIdx.x;
    const int tx = tid & 15;           // n sub-tile
    const int ty = tid >> 4;           // m sub-tile
    const int lrow = tid >> 2;         // 0..63 loader row
    const int lk = (tid & 3) << 2;     // k offset 0,4,8,12
    const int bn = blockIdx.x * BN;
    const int bm = blockIdx.y * BM;

    const float* Aptr = A + (size_t)(bm)*K_TOT;
    const float* Bptr = Bw + (size_t)(bn)*K_TOT;

    ull acc[8][4];
#pragma unroll
    for (int i = 0; i < 8; i++)
#pragma unroll
        for (int j = 0; j < 4; j++) acc[i][j] = 0ull;

    // Prologue: stage chunk 0 in registers
    float4 ra0, ra1, rb0, rb1;
    {
        ra0 = *reinterpret_cast<const float4*>(Aptr + (size_t)lrow * K_TOT + lk);
        ra1 = *reinterpret_cast<const float4*>(Aptr + (size_t)(lrow + 64) * K_TOT + lk);
        rb0 = *reinterpret_cast<const float4*>(Bptr + (size_t)lrow * K_TOT + lk);
        rb1 = *reinterpret_cast<const float4*>(Bptr + (size_t)(lrow + 64) * K_TOT + lk);
    }

    for (int c = 0; c < NCHUNK; c++) {
        {
            const float av0[4] = {ra0.x, ra0.y, ra0.z, ra0.w};
            const float av1[4] = {ra1.x, ra1.y, ra1.z, ra1.w};
            const float bv0[4] = {rb0.x, rb0.y, rb0.z, rb0.w};
            const float bv1[4] = {rb1.x, rb1.y, rb1.z, rb1.w};
#pragma unroll
            for (int q = 0; q < 4; q++) {
                *reinterpret_cast<float2*>(&As[lk + q][2 * lrow]) =
                    make_float2(av0[q], av0[q]);
                *reinterpret_cast<float2*>(&As[lk + q][2 * (lrow + 64)]) =
                    make_float2(av1[q], av1[q]);
                Bs[lk + q][lrow] = bv0[q];
                Bs[lk + q][lrow + 64] = bv1[q];
            }
        }
        __syncthreads();

        if (c + 1 < NCHUNK) {
            const int ko = (c + 1) * BK + lk;
            ra0 = *reinterpret_cast<const float4*>(Aptr + (size_t)lrow * K_TOT + ko);
            ra1 = *reinterpret_cast<const float4*>(Aptr + (size_t)(lrow + 64) * K_TOT + ko);
            rb0 = *reinterpret_cast<const float4*>(Bptr + (size_t)lrow * K_TOT + ko);
            rb1 = *reinterpret_cast<const float4*>(Bptr + (size_t)(lrow + 64) * K_TOT + ko);
        }

#pragma unroll
        for (int kk = 0; kk < BK; kk++) {
            const ull* bp = reinterpret_cast<const ull*>(&Bs[kk][tx * 8]);
            ull bv0 = bp[0], bv1 = bp[1], bv2 = bp[2], bv3 = bp[3];
            const ull* ap = reinterpret_cast<const ull*>(&As[kk][ty * 16]);
#pragma unroll
            for (int i = 0; i < 8; i++) {
                ull av = ap[i];
                ffma2(acc[i][0], av, bv0);
                ffma2(acc[i][1], av, bv1);
                ffma2(acc[i][2], av, bv2);
                ffma2(acc[i][3], av, bv3);
            }
        }
        __syncthreads();
    }

    // Epilogue: unpack, add bias, store
#pragma unroll
    for (int i = 0; i < 8; i++) {
        const int row = bm + ty * 8 + i;
        float* orow = g_h + (size_t)row * N_TOT + bn + tx * 8;
#pragma unroll
        for (int j = 0; j < 2; j++) {
            float4 o;
            o.x = __uint_as_float((unsigned)(acc[i][2 * j] & 0xffffffffu));
            o.y = __uint_as_float((unsigned)(acc[i][2 * j] >> 32));
            o.z = __uint_as_float((unsigned)(acc[i][2 * j + 1] & 0xffffffffu));
            o.w = __uint_as_float((unsigned)(acc[i][2 * j + 1] >> 32));
            const int cb = bn + tx * 8 + 4 * j;
            o.x += __ldg(bias + cb + 0);
            o.y += __ldg(bias + cb + 1);
            o.z += __ldg(bias + cb + 2);
            o.w += __ldg(bias + cb + 3);
            *reinterpret_cast<float4*>(orow + 4 * j) = o;
        }
    }
}

// ---------------------------------------------------------------------------
// LIF scan: 2 neurons per thread (float2), sequential over T, unroll 16.
// Per-element arithmetic identical to the passing rounds:
//   v = fma(0.5,v,h) == v - v/2 + h exactly; spike at v>=1; hard reset to 0.
// 64-thread blocks -> 512 blocks (3.46 waves over 148 SMs, balanced).
// ---------------------------------------------------------------------------
__global__ __launch_bounds__(64)
void lif_scan_kernel(float* __restrict__ out) {
    const int idx = blockIdx.x * 64 + (int)threadIdx.x;   // 0..32767 pairs
    const float2* hp = reinterpret_cast<const float2*>(g_h) + idx;
    float2* op = reinterpret_cast<float2*>(out) + idx;
    float vx = 0.0f, vy = 0.0f;

#pragma unroll 1
    for (int t = 0; t < T_STEPS; t += 16) {
        float2 h[16];
#pragma unroll
        for (int k = 0; k < 16; k++) h[k] = __ldcg(hp + (size_t)k * BH2);
        float2 sp[16];
#pragma unroll
        for (int k = 0; k < 16; k++) {
            vx = fmaf(0.5f, vx, h[k].x);
            vy = fmaf(0.5f, vy, h[k].y);
            const bool fx = (vx >= 1.0f);
            const bool fy = (vy >= 1.0f);
            sp[k].x = fx ? 1.0f : 0.0f;
            sp[k].y = fy ? 1.0f : 0.0f;
            vx = fx ? 0.0f : vx;
            vy = fy ? 0.0f : vy;
        }
#pragma unroll
        for (int k = 0; k < 16; k++) __stcg(op + (size_t)k * BH2, sp[k]);
        hp += (size_t)16 * BH2;
        op += (size_t)16 * BH2;
    }
}

// ---------------------------------------------------------------------------
extern "C" void kernel_launch(void* const* d_in, const int* in_sizes, int n_in,
                              void* d_out, int out_size) {
    const float* x = (const float*)d_in[0];   // (256,128,512)
    const float* W = (const float*)d_in[1];   // (512,512)
    const float* b = (const float*)d_in[2];   // (512,)
    float* out = (float*)d_out;               // (256,128,512)

    dim3 ggrid(N_TOT / BN, M_TOT / BM);       // (4, 256)
    gemm_bias_kernel<<<ggrid, 256>>>(x, W, b);

    lif_scan_kernel<<<BH2 / 64, 64>>>(out);
}

// round 11
// speedup vs baseline: 1.1298x; 1.1298x over previous
#include <cuda_runtime.h>
#include <cstdint>

// LIF spiking layer: h = x @ W^T + b (M=32768, N=512, K=512), LIF scan over T.
//
// Strategy (R9): fast tf32x4 HMMA GEMM (ordering noise ~1e-6 flips ~24 spikes)
// + exact fp32 fix-up of only the neurons whose membrane potential ever comes
// within MARGIN of threshold (those are the only possible flips). Fix-up
// reproduces the bit-exact sequential-k fp32 chain that gave rel_err 0.0.

#define M_TOT 32768
#define N_TOT 512
#define K_TOT 512
#define T_STEPS 256
#define BH 65536
#define MARGIN 3e-5f

#define BM 128
#define BN 128
#define BK 32
#define NCHUNK (K_TOT / BK)          // 16
#define LDK 36
#define TILE_WORDS (128 * LDK)
#define STAGE_WORDS (4 * TILE_WORDS)
#define SMEM_DYN (2 * STAGE_WORDS * 4)

// Scratch (device globals; allocation forbidden)
__device__ float g_h[M_TOT * N_TOT];    // 64 MB
__device__ float g_xhi[M_TOT * K_TOT];  // 64 MB
__device__ float g_xlo[M_TOT * K_TOT];  // 64 MB
__device__ float g_whi[N_TOT * K_TOT];  // 1 MB
__device__ float g_wlo[N_TOT * K_TOT];  // 1 MB
__device__ int g_list[BH];
__device__ int g_count;

// ---------------------------------------------------------------------------
__device__ __forceinline__ uint32_t smem_u32(const void* p) {
    uint32_t a;
    asm("{ .reg .u64 t; cvta.to.shared.u64 t, %1; cvt.u32.u64 %0, t; }"
        : "=r"(a) : "l"(p));
    return a;
}
__device__ __forceinline__ void cp16(uint32_t s, const void* g) {
    asm volatile("cp.async.cg.shared.global [%0], [%1], 16;" :: "r"(s), "l"(g));
}
#define CP_COMMIT() asm volatile("cp.async.commit_group;" ::: "memory")
#define CP_WAIT1() asm volatile("cp.async.wait_group 1;" ::: "memory")
#define CP_WAIT0() asm volatile("cp.async.wait_group 0;" ::: "memory")

__device__ __forceinline__ void mma_tf32(float* d, const float* a, const float* b) {
    asm volatile(
        "mma.sync.aligned.m16n8k8.row.col.f32.tf32.tf32.f32 "
        "{%0,%1,%2,%3}, {%4,%5,%6,%7}, {%8,%9}, {%0,%1,%2,%3};"
        : "+f"(d[0]), "+f"(d[1]), "+f"(d[2]), "+f"(d[3])
        : "r"(__float_as_uint(a[0])), "r"(__float_as_uint(a[1])),
          "r"(__float_as_uint(a[2])), "r"(__float_as_uint(a[3])),
          "r"(__float_as_uint(b[0])), "r"(__float_as_uint(b[1])));
}
__device__ __forceinline__ float tf32_rna(float x) {
    uint32_t u;
    asm("cvt.rna.tf32.f32 %0, %1;" : "=r"(u) : "f"(x));
    return __uint_as_float(u);
}

// ---------------------------------------------------------------------------
// Phase 0: split fp32 -> (tf32 hi, tf32 lo)
// ---------------------------------------------------------------------------
__global__ __launch_bounds__(256)
void split_kernel(const float* __restrict__ src, float* __restrict__ hi,
                  float* __restrict__ lo, int n4) {
    int i = blockIdx.x * blockDim.x + threadIdx.x;
    if (i >= n4) return;
    float4 v = reinterpret_cast<const float4*>(src)[i];
    float4 h, l;
    h.x = tf32_rna(v.x); l.x = tf32_rna(v.x - h.x);
    h.y = tf32_rna(v.y); l.y = tf32_rna(v.y - h.y);
    h.z = tf32_rna(v.z); l.z = tf32_rna(v.z - h.z);
    h.w = tf32_rna(v.w); l.w = tf32_rna(v.w - h.w);
    reinterpret_cast<float4*>(hi)[i] = h;
    reinterpret_cast<float4*>(lo)[i] = l;
}

__global__ void init_count_kernel() {
    if (threadIdx.x == 0) g_count = 0;
}

// ---------------------------------------------------------------------------
// Phase 1: tf32x4 GEMM via mma.sync (layout proven in round 4).
// CTA 128x128, 8 warps (4m x 2n), warp tile 32x64, BK=32, 2-stage cp.async.
// ---------------------------------------------------------------------------
__global__ __launch_bounds__(256, 1)
void gemm_tf32_kernel(const float* __restrict__ bias) {
    extern __shared__ float smf[];
    const uint32_t sbase = smem_u32(smf);

    const int tid = (int)threadIdx.x;
    const int wid = tid >> 5;
    const int lane = tid & 31;
    const int l4 = lane >> 2;
    const int lk = lane & 3;
    const int warp_m = wid >> 1;
    const int warp_n = wid & 1;
    const int bn = blockIdx.x * BN;
    const int bm = blockIdx.y * BM;

    float acc[2][8][4];
#pragma unroll
    for (int mf = 0; mf < 2; mf++)
#pragma unroll
        for (int nf = 0; nf < 8; nf++)
#pragma unroll
            for (int q = 0; q < 4; q++) acc[mf][nf][q] = 0.0f;

    auto fill = [&](int s, int c) {
        const uint32_t st = sbase + (uint32_t)(s * STAGE_WORDS) * 4u;
        const uint32_t uAhi = st;
        const uint32_t uAlo = st + TILE_WORDS * 4u;
        const uint32_t uBhi = st + 2u * TILE_WORDS * 4u;
        const uint32_t uBlo = st + 3u * TILE_WORDS * 4u;
        const int kbase = c * BK;
#pragma unroll
        for (int i = tid; i < 1024; i += 256) {
            const int r = i >> 3, q = i & 7;
            const uint32_t doff = (uint32_t)(r * LDK + q * 4) * 4u;
            const size_t aoff = (size_t)(bm + r) * K_TOT + kbase + q * 4;
            const size_t boff = (size_t)(bn + r) * K_TOT + kbase + q * 4;
            cp16(uAhi + doff, g_xhi + aoff);
            cp16(uAlo + doff, g_xlo + aoff);
            cp16(uBhi + doff, g_whi + boff);
            cp16(uBlo + doff, g_wlo + boff);
        }
    };

    auto compute = [&](int s) {
        const float* As_hi = smf + s * STAGE_WORDS;
        const float* As_lo = As_hi + TILE_WORDS;
        const float* Bs_hi = As_hi + 2 * TILE_WORDS;
        const float* Bs_lo = As_hi + 3 * TILE_WORDS;
        const int arow = warp_m * 32 + l4;
        const int nrow = warp_n * 64 + l4;
#pragma unroll
        for (int k8 = 0; k8 < 4; k8++) {
            const int ko = k8 * 8 + lk;
            float ah[2][4], al[2][4];
#pragma unroll
            for (int mf = 0; mf < 2; mf++) {
                const int r0 = (arow + mf * 16) * LDK + ko;
                ah[mf][0] = As_hi[r0];
                ah[mf][1] = As_hi[r0 + 8 * LDK];
                ah[mf][2] = As_hi[r0 + 4];
                ah[mf][3] = As_hi[r0 + 8 * LDK + 4];
                al[mf][0] = As_lo[r0];
                al[mf][1] = As_lo[r0 + 8 * LDK];
                al[mf][2] = As_lo[r0 + 4];
                al[mf][3] = As_lo[r0 + 8 * LDK + 4];
            }
            float bh[8][2], bl[8][2];
#pragma unroll
            for (int nf = 0; nf < 8; nf++) {
                const int n0 = (nrow + nf * 8) * LDK + ko;
                bh[nf][0] = Bs_hi[n0];
                bh[nf][1] = Bs_hi[n0 + 4];
                bl[nf][0] = Bs_lo[n0];
                bl[nf][1] = Bs_lo[n0 + 4];
            }
#pragma unroll
            for (int mf = 0; mf < 2; mf++)
#pragma unroll
                for (int nf = 0; nf < 8; nf++) {
                    mma_tf32(acc[mf][nf], ah[mf], bh[nf]);
                    mma_tf32(acc[mf][nf], ah[mf], bl[nf]);
                    mma_tf32(acc[mf][nf], al[mf], bh[nf]);
                    mma_tf32(acc[mf][nf], al[mf], bl[nf]);
                }
        }
    };

    fill(0, 0);
    CP_COMMIT();
    for (int c = 0; c < NCHUNK; c++) {
        if (c + 1 < NCHUNK) {
            fill((c + 1) & 1, c + 1);
            CP_COMMIT();
            CP_WAIT1();
        } else {
            CP_WAIT0();
        }
        __syncthreads();
        compute(c & 1);
        __syncthreads();
    }

#pragma unroll
    for (int nf = 0; nf < 8; nf++) {
        const int col = bn + warp_n * 64 + nf * 8 + lk * 2;
        const float b0 = __ldg(bias + col);
        const float b1 = __ldg(bias + col + 1);
#pragma unroll
        for (int mf = 0; mf < 2; mf++) {
            const int row = bm + warp_m * 32 + mf * 16 + l4;
            float2 v0 = make_float2(acc[mf][nf][0] + b0, acc[mf][nf][1] + b1);
            float2 v1 = make_float2(acc[mf][nf][2] + b0, acc[mf][nf][3] + b1);
            *reinterpret_cast<float2*>(g_h + (size_t)row * N_TOT + col) = v0;
            *reinterpret_cast<float2*>(g_h + (size_t)(row + 8) * N_TOT + col) = v1;
        }
    }
}

// ---------------------------------------------------------------------------
// Phase 2: LIF scan + near-threshold flagging.
//   v = fma(0.5,v,h); spike v>=1; hard reset. Flag if |v-1| < MARGIN ever.
// ---------------------------------------------------------------------------
__global__ __launch_bounds__(256)
void lif_scan_flag_kernel(float* __restrict__ out) {
    const int idx = blockIdx.x * 256 + (int)threadIdx.x;
    const float* hp = g_h + idx;
    float* op = out + idx;
    float v = 0.0f;
    bool flag = false;

#pragma unroll 1
    for (int t = 0; t < T_STEPS; t += 16) {
        float h[16];
#pragma unroll
        for (int k = 0; k < 16; k++) h[k] = __ldcg(hp + (size_t)k * BH);
        float sp[16];
#pragma unroll
        for (int k = 0; k < 16; k++) {
            v = fmaf(0.5f, v, h[k]);
            flag = flag || (fabsf(v - 1.0f) < MARGIN);
            const bool f = (v >= 1.0f);
            sp[k] = f ? 1.0f : 0.0f;
            v = f ? 0.0f : v;
        }
#pragma unroll
        for (int k = 0; k < 16; k++) __stcg(op + (size_t)k * BH, sp[k]);
        hp += (size_t)16 * BH;
        op += (size_t)16 * BH;
    }

    if (flag) {
        int p = atomicAdd(&g_count, 1);
        g_list[p] = idx;
    }
}

// ---------------------------------------------------------------------------
// Phase 3: exact fix-up of flagged neurons. One block per flagged neuron
// (grid-strided). Thread t computes h[t] = seq-k fp32 dot + bias (bit-exact
// match of the reference / round-1 chain), then thread 0 redoes the scan.
// ---------------------------------------------------------------------------
__global__ __launch_bounds__(256)
void fixup_kernel(const float* __restrict__ x, const float* __restrict__ W,
                  const float* __restrict__ bias, float* __restrict__ out) {
    __shared__ float sW[K_TOT];
    __shared__ float sh[T_STEPS];

    for (int i = blockIdx.x; i < g_count; i += gridDim.x) {
        const int idx = g_list[i];
        const int b = idx >> 9;        // idx = b*512 + hid
        const int hid = idx & 511;

        for (int k = threadIdx.x; k < K_TOT; k += 256)
            sW[k] = W[(size_t)hid * K_TOT + k];
        __syncthreads();

        const int t = (int)threadIdx.x;   // 0..255 == T_STEPS
        const float4* xr = reinterpret_cast<const float4*>(
            x + ((size_t)t * 128 + b) * K_TOT);
        float acc = 0.0f;
#pragma unroll 4
        for (int k4 = 0; k4 < K_TOT / 4; k4++) {
            const float4 xx = __ldg(xr + k4);
            acc = fmaf(xx.x, sW[k4 * 4 + 0], acc);
            acc = fmaf(xx.y, sW[k4 * 4 + 1], acc);
            acc = fmaf(xx.z, sW[k4 * 4 + 2], acc);
            acc = fmaf(xx.w, sW[k4 * 4 + 3], acc);
        }
        sh[t] = acc + __ldg(bias + hid);
        __syncthreads();

        if (threadIdx.x == 0) {
            float v = 0.0f;
#pragma unroll 1
            for (int t2 = 0; t2 < T_STEPS; t2++) {
                v = fmaf(0.5f, v, sh[t2]);
                const bool f = (v >= 1.0f);
                out[(size_t)t2 * BH + idx] = f ? 1.0f : 0.0f;
                v = f ? 0.0f : v;
            }
        }
        __syncthreads();
    }
}

// ---------------------------------------------------------------------------
extern "C" void kernel_launch(void* const* d_in, const int* in_sizes, int n_in,
                              void* d_out, int out_size) {
    const float* x = (const float*)d_in[0];   // (256,128,512)
    const float* W = (const float*)d_in[1];   // (512,512)
    const float* b = (const float*)d_in[2];   // (512,)
    float* out = (float*)d_out;               // (256,128,512)

    float *xhi, *xlo, *whi, *wlo;
    cudaGetSymbolAddress((void**)&xhi, g_xhi);
    cudaGetSymbolAddress((void**)&xlo, g_xlo);
    cudaGetSymbolAddress((void**)&whi, g_whi);
    cudaGetSymbolAddress((void**)&wlo, g_wlo);

    cudaFuncSetAttribute(gemm_tf32_kernel,
                         cudaFuncAttributeMaxDynamicSharedMemorySize, SMEM_DYN);

    const int n4x = M_TOT * K_TOT / 4;
    const int n4w = N_TOT * K_TOT / 4;
    split_kernel<<<(n4x + 255) / 256, 256>>>(x, xhi, xlo, n4x);
    split_kernel<<<(n4w + 255) / 256, 256>>>(W, whi, wlo, n4w);
    init_count_kernel<<<1, 32>>>();

    dim3 grid(N_TOT / BN, M_TOT / BM);  // (4, 256)
    gemm_tf32_kernel<<<grid, 256, SMEM_DYN>>>(b);

    lif_scan_flag_kernel<<<BH / 256, 256>>>(out);

    fixup_kernel<<<256, 256>>>(x, W, b, out);
}

// round 14
// speedup vs baseline: 1.3915x; 1.2316x over previous
#include <cuda_runtime.h>
#include <cstdint>

// LIF spiking layer: h = x @ W^T + b (M=32768, N=512, K=512), LIF scan over T.
//
// R11: tf32x3 HMMA GEMM (hihi + hilo + lohi; lolo term ~2e-7 rms, absorbed by
// the validated flag+fixup margin) with on-the-fly A split from raw x (no
// x-split kernel, half the fill traffic), 3-stage cp.async pipeline.
// Near-threshold neurons (|v-1| < 3e-5) are recomputed with the bit-exact
// sequential-k fp32 chain -> rel_err 0.0 (validated R10).

#define M_TOT 32768
#define N_TOT 512
#define K_TOT 512
#define T_STEPS 256
#define BH 65536
#define MARGIN 3e-5f

#define BM 128
#define BN 128
#define BK 32
#define NCHUNK (K_TOT / BK)          // 16
#define LDK 36
#define TILE_W (128 * LDK)           // 4608 words (A raw / Bhi / Blo each)
#define STAGE_W (3 * TILE_W)         // 13824 words = 55296 B
#define NSTAGE 3
#define SMEM_DYN (NSTAGE * STAGE_W * 4)   // 165888 B

// Scratch (device globals; allocation forbidden)
__device__ float g_h[M_TOT * N_TOT];    // 64 MB
__device__ float g_whi[N_TOT * K_TOT];  // 1 MB
__device__ float g_wlo[N_TOT * K_TOT];  // 1 MB
__device__ int g_list[BH];
__device__ int g_count;

// ---------------------------------------------------------------------------
__device__ __forceinline__ uint32_t smem_u32(const void* p) {
    uint32_t a;
    asm("{ .reg .u64 t; cvta.to.shared.u64 t, %1; cvt.u32.u64 %0, t; }"
        : "=r"(a) : "l"(p));
    return a;
}
__device__ __forceinline__ void cp16(uint32_t s, const void* g) {
    asm volatile("cp.async.cg.shared.global [%0], [%1], 16;" :: "r"(s), "l"(g));
}
#define CP_COMMIT() asm volatile("cp.async.commit_group;" ::: "memory")
#define CP_WAIT1() asm volatile("cp.async.wait_group 1;" ::: "memory")
#define CP_WAIT0() asm volatile("cp.async.wait_group 0;" ::: "memory")

__device__ __forceinline__ void mma_tf32(float* d, const float* a, const float* b) {
    asm volatile(
        "mma.sync.aligned.m16n8k8.row.col.f32.tf32.tf32.f32 "
        "{%0,%1,%2,%3}, {%4,%5,%6,%7}, {%8,%9}, {%0,%1,%2,%3};"
        : "+f"(d[0]), "+f"(d[1]), "+f"(d[2]), "+f"(d[3])
        : "r"(__float_as_uint(a[0])), "r"(__float_as_uint(a[1])),
          "r"(__float_as_uint(a[2])), "r"(__float_as_uint(a[3])),
          "r"(__float_as_uint(b[0])), "r"(__float_as_uint(b[1])));
}
__device__ __forceinline__ float tf32_rna(float x) {
    uint32_t u;
    asm("cvt.rna.tf32.f32 %0, %1;" : "=r"(u) : "f"(x));
    return __uint_as_float(u);
}

// ---------------------------------------------------------------------------
// Phase 0: split W -> (tf32 hi, tf32 lo). Tiny (1 MB).
// ---------------------------------------------------------------------------
__global__ __launch_bounds__(256)
void split_kernel(const float* __restrict__ src, float* __restrict__ hi,
                  float* __restrict__ lo, int n4) {
    int i = blockIdx.x * blockDim.x + threadIdx.x;
    if (i >= n4) return;
    float4 v = reinterpret_cast<const float4*>(src)[i];
    float4 h, l;
    h.x = tf32_rna(v.x); l.x = tf32_rna(v.x - h.x);
    h.y = tf32_rna(v.y); l.y = tf32_rna(v.y - h.y);
    h.z = tf32_rna(v.z); l.z = tf32_rna(v.z - h.z);
    h.w = tf32_rna(v.w); l.w = tf32_rna(v.w - h.w);
    reinterpret_cast<float4*>(hi)[i] = h;
    reinterpret_cast<float4*>(lo)[i] = l;
}

__global__ void init_count_kernel() {
    if (threadIdx.x == 0) g_count = 0;
}

// ---------------------------------------------------------------------------
// Phase 1: tf32x3 GEMM via mma.sync. CTA 128x128, 8 warps (4m x 2n), warp
// tile 32x64, BK=32, 3-stage cp.async pipeline. A loaded RAW, split to
// (hi, lo) in registers per fragment (bitwise same values as a pre-split).
// ---------------------------------------------------------------------------
__global__ __launch_bounds__(256, 1)
void gemm_tf32_kernel(const float* __restrict__ x, const float* __restrict__ bias) {
    extern __shared__ float smf[];
    const uint32_t sbase = smem_u32(smf);

    const int tid = (int)threadIdx.x;
    const int wid = tid >> 5;
    const int lane = tid & 31;
    const int l4 = lane >> 2;
    const int lk = lane & 3;
    const int warp_m = wid >> 1;   // 0..3
    const int warp_n = wid & 1;    // 0..1
    const int bn = blockIdx.x * BN;
    const int bm = blockIdx.y * BM;

    float acc[2][8][4];
#pragma unroll
    for (int mf = 0; mf < 2; mf++)
#pragma unroll
        for (int nf = 0; nf < 8; nf++)
#pragma unroll
            for (int q = 0; q < 4; q++) acc[mf][nf][q] = 0.0f;

    auto fill = [&](int s, int c) {
        const uint32_t st = sbase + (uint32_t)(s * STAGE_W) * 4u;
        const uint32_t uBhi = st + (uint32_t)TILE_W * 4u;
        const uint32_t uBlo = st + (uint32_t)(2 * TILE_W) * 4u;
        const int kbase = c * BK;
        // A raw: 128 rows x 8 granules
#pragma unroll
        for (int i = tid; i < 1024; i += 256) {
            const int r = i >> 3, q = i & 7;
            const uint32_t doff = (uint32_t)(r * LDK + q * 4) * 4u;
            cp16(st + doff, x + (size_t)(bm + r) * K_TOT + kbase + q * 4);
        }
        // B hi/lo: 2 arrays x 128 rows x 8
#pragma unroll
        for (int i = tid; i < 2048; i += 256) {
            const int arr = i >> 10, rem = i & 1023;
            const int r = rem >> 3, q = rem & 7;
            const uint32_t doff = (uint32_t)(r * LDK + q * 4) * 4u;
            const float* wsrc = arr ? g_wlo : g_whi;
            cp16((arr ? uBlo : uBhi) + doff,
                 wsrc + (size_t)(bn + r) * K_TOT + kbase + q * 4);
        }
    };

    auto compute = [&](int s) {
        const float* As = smf + s * STAGE_W;          // raw A
        const float* Bs_hi = As + TILE_W;
        const float* Bs_lo = As + 2 * TILE_W;
        const int arow = warp_m * 32 + l4;
        const int nrow = warp_n * 64 + l4;
#pragma unroll
        for (int k8 = 0; k8 < 4; k8++) {
            const int ko = k8 * 8 + lk;
            float ah[2][4], al[2][4];
#pragma unroll
            for (int mf = 0; mf < 2; mf++) {
                const int r0 = (arow + mf * 16) * LDK + ko;
                float a0 = As[r0];
                float a1 = As[r0 + 8 * LDK];
                float a2 = As[r0 + 4];
                float a3 = As[r0 + 8 * LDK + 4];
                ah[mf][0] = tf32_rna(a0); al[mf][0] = tf32_rna(a0 - ah[mf][0]);
                ah[mf][1] = tf32_rna(a1); al[mf][1] = tf32_rna(a1 - ah[mf][1]);
                ah[mf][2] = tf32_rna(a2); al[mf][2] = tf32_rna(a2 - ah[mf][2]);
                ah[mf][3] = tf32_rna(a3); al[mf][3] = tf32_rna(a3 - ah[mf][3]);
            }
            float bh[8][2], bl[8][2];
#pragma unroll
            for (int nf = 0; nf < 8; nf++) {
                const int n0 = (nrow + nf * 8) * LDK + ko;
                bh[nf][0] = Bs_hi[n0];
                bh[nf][1] = Bs_hi[n0 + 4];
                bl[nf][0] = Bs_lo[n0];
                bl[nf][1] = Bs_lo[n0 + 4];
            }
#pragma unroll
            for (int mf = 0; mf < 2; mf++)
#pragma unroll
                for (int nf = 0; nf < 8; nf++) {
                    mma_tf32(acc[mf][nf], ah[mf], bh[nf]);
                    mma_tf32(acc[mf][nf], ah[mf], bl[nf]);
                    mma_tf32(acc[mf][nf], al[mf], bh[nf]);
                }
        }
    };

    // 3-stage pipeline
    fill(0, 0);
    CP_COMMIT();
    fill(1, 1);
    CP_COMMIT();
    for (int c = 0; c < NCHUNK; c++) {
        if (c + 2 <= NCHUNK) { CP_WAIT1(); } else { CP_WAIT0(); }
        __syncthreads();
        if (c + 2 < NCHUNK) {
            fill((c + 2) % NSTAGE, c + 2);
            CP_COMMIT();
        }
        compute(c % NSTAGE);
    }

    // Epilogue: + bias -> g_h
#pragma unroll
    for (int nf = 0; nf < 8; nf++) {
        const int col = bn + warp_n * 64 + nf * 8 + lk * 2;
        const float b0 = __ldg(bias + col);
        const float b1 = __ldg(bias + col + 1);
#pragma unroll
        for (int mf = 0; mf < 2; mf++) {
            const int row = bm + warp_m * 32 + mf * 16 + l4;
            float2 v0 = make_float2(acc[mf][nf][0] + b0, acc[mf][nf][1] + b1);
            float2 v1 = make_float2(acc[mf][nf][2] + b0, acc[mf][nf][3] + b1);
            *reinterpret_cast<float2*>(g_h + (size_t)row * N_TOT + col) = v0;
            *reinterpret_cast<float2*>(g_h + (size_t)(row + 8) * N_TOT + col) = v1;
        }
    }
}

// ---------------------------------------------------------------------------
// Phase 2: LIF scan + near-threshold flagging.
// ---------------------------------------------------------------------------
__global__ __launch_bounds__(256)
void lif_scan_flag_kernel(float* __restrict__ out) {
    const int idx = blockIdx.x * 256 + (int)threadIdx.x;
    const float* hp = g_h + idx;
    float* op = out + idx;
    float v = 0.0f;
    bool flag = false;

#pragma unroll 1
    for (int t = 0; t < T_STEPS; t += 16) {
        float h[16];
#pragma unroll
        for (int k = 0; k < 16; k++) h[k] = __ldcg(hp + (size_t)k * BH);
        float sp[16];
#pragma unroll
        for (int k = 0; k < 16; k++) {
            v = fmaf(0.5f, v, h[k]);
            flag = flag || (fabsf(v - 1.0f) < MARGIN);
            const bool f = (v >= 1.0f);
            sp[k] = f ? 1.0f : 0.0f;
            v = f ? 0.0f : v;
        }
#pragma unroll
        for (int k = 0; k < 16; k++) __stcg(op + (size_t)k * BH, sp[k]);
        hp += (size_t)16 * BH;
        op += (size_t)16 * BH;
    }

    if (flag) {
        int p = atomicAdd(&g_count, 1);
        g_list[p] = idx;
    }
}

// ---------------------------------------------------------------------------
// Phase 3: exact fix-up of flagged neurons (bit-exact sequential fp32 chain).
// ---------------------------------------------------------------------------
__global__ __launch_bounds__(256)
void fixup_kernel(const float* __restrict__ x, const float* __restrict__ W,
                  const float* __restrict__ bias, float* __restrict__ out) {
    __shared__ float sW[K_TOT];
    __shared__ float sh[T_STEPS];

    for (int i = blockIdx.x; i < g_count; i += gridDim.x) {
        const int idx = g_list[i];
        const int b = idx >> 9;
        const int hid = idx & 511;

        for (int k = threadIdx.x; k < K_TOT; k += 256)
            sW[k] = W[(size_t)hid * K_TOT + k];
        __syncthreads();

        const int t = (int)threadIdx.x;
        const float4* xr = reinterpret_cast<const float4*>(
            x + ((size_t)t * 128 + b) * K_TOT);
        float acc = 0.0f;
#pragma unroll 4
        for (int k4 = 0; k4 < K_TOT / 4; k4++) {
            const float4 xx = __ldg(xr + k4);
            acc = fmaf(xx.x, sW[k4 * 4 + 0], acc);
            acc = fmaf(xx.y, sW[k4 * 4 + 1], acc);
            acc = fmaf(xx.z, sW[k4 * 4 + 2], acc);
            acc = fmaf(xx.w, sW[k4 * 4 + 3], acc);
        }
        sh[t] = acc + __ldg(bias + hid);
        __syncthreads();

        if (threadIdx.x == 0) {
            float v = 0.0f;
#pragma unroll 1
            for (int t2 = 0; t2 < T_STEPS; t2++) {
                v = fmaf(0.5f, v, sh[t2]);
                const bool f = (v >= 1.0f);
                out[(size_t)t2 * BH + idx] = f ? 1.0f : 0.0f;
                v = f ? 0.0f : v;
            }
        }
        __syncthreads();
    }
}

// ---------------------------------------------------------------------------
extern "C" void kernel_launch(void* const* d_in, const int* in_sizes, int n_in,
                              void* d_out, int out_size) {
    const float* x = (const float*)d_in[0];   // (256,128,512)
    const float* W = (const float*)d_in[1];   // (512,512)
    const float* b = (const float*)d_in[2];   // (512,)
    float* out = (float*)d_out;               // (256,128,512)

    float *whi, *wlo;
    cudaGetSymbolAddress((void**)&whi, g_whi);
    cudaGetSymbolAddress((void**)&wlo, g_wlo);

    cudaFuncSetAttribute(gemm_tf32_kernel,
                         cudaFuncAttributeMaxDynamicSharedMemorySize, SMEM_DYN);

    const int n4w = N_TOT * K_TOT / 4;
    split_kernel<<<(n4w + 255) / 256, 256>>>(W, whi, wlo, n4w);
    init_count_kernel<<<1, 32>>>();

    dim3 grid(N_TOT / BN, M_TOT / BM);  // (4, 256)
    gemm_tf32_kernel<<<grid, 256, SMEM_DYN>>>(x, b);

    lif_scan_flag_kernel<<<BH / 256, 256>>>(out);

    fixup_kernel<<<256, 256>>>(x, W, b, out);
}

// round 15
// speedup vs baseline: 1.4233x; 1.0229x over previous
#include <cuda_runtime.h>
#include <cstdint>

// LIF spiking layer: h = x @ W^T + b (M=32768, N=512, K=512), LIF scan over T.
//
// R14: tf32x3 HMMA GEMM (hihi+hilo+lohi) with on-the-fly A split, BK=64 and
// a 2-stage pipeline (104 KB/stage) -> half the barrier epochs of R11.
// Near-threshold neurons (|v-1| < 3e-5) recomputed with the bit-exact
// sequential-k fp32 chain (validated: rel_err 0.0).

#define M_TOT 32768
#define N_TOT 512
#define K_TOT 512
#define T_STEPS 256
#define BH 65536
#define MARGIN 3e-5f

#define BM 128
#define BN 128
#define BK 64
#define NCHUNK (K_TOT / BK)          // 8
#define LDK 68                       // 68 % 32 == 4 -> conflict-free like LDK 36
#define TILE_W (128 * LDK)           // 8704 words
#define STAGE_W (3 * TILE_W)         // 26112 words = 104448 B
#define NSTAGE 2
#define SMEM_DYN (NSTAGE * STAGE_W * 4)   // 208896 B

// Scratch (device globals; allocation forbidden)
__device__ float g_h[M_TOT * N_TOT];    // 64 MB
__device__ float g_whi[N_TOT * K_TOT];  // 1 MB
__device__ float g_wlo[N_TOT * K_TOT];  // 1 MB
__device__ int g_list[BH];
__device__ int g_count;

// ---------------------------------------------------------------------------
__device__ __forceinline__ uint32_t smem_u32(const void* p) {
    uint32_t a;
    asm("{ .reg .u64 t; cvta.to.shared.u64 t, %1; cvt.u32.u64 %0, t; }"
        : "=r"(a) : "l"(p));
    return a;
}
__device__ __forceinline__ void cp16(uint32_t s, const void* g) {
    asm volatile("cp.async.cg.shared.global [%0], [%1], 16;" :: "r"(s), "l"(g));
}
#define CP_COMMIT() asm volatile("cp.async.commit_group;" ::: "memory")
#define CP_WAIT1() asm volatile("cp.async.wait_group 1;" ::: "memory")
#define CP_WAIT0() asm volatile("cp.async.wait_group 0;" ::: "memory")

__device__ __forceinline__ void mma_tf32(float* d, const float* a, const float* b) {
    asm volatile(
        "mma.sync.aligned.m16n8k8.row.col.f32.tf32.tf32.f32 "
        "{%0,%1,%2,%3}, {%4,%5,%6,%7}, {%8,%9}, {%0,%1,%2,%3};"
        : "+f"(d[0]), "+f"(d[1]), "+f"(d[2]), "+f"(d[3])
        : "r"(__float_as_uint(a[0])), "r"(__float_as_uint(a[1])),
          "r"(__float_as_uint(a[2])), "r"(__float_as_uint(a[3])),
          "r"(__float_as_uint(b[0])), "r"(__float_as_uint(b[1])));
}
__device__ __forceinline__ float tf32_rna(float x) {
    uint32_t u;
    asm("cvt.rna.tf32.f32 %0, %1;" : "=r"(u) : "f"(x));
    return __uint_as_float(u);
}

// ---------------------------------------------------------------------------
// Phase 0: split W -> (tf32 hi, tf32 lo). Tiny (1 MB).
// ---------------------------------------------------------------------------
__global__ __launch_bounds__(256)
void split_kernel(const float* __restrict__ src, float* __restrict__ hi,
                  float* __restrict__ lo, int n4) {
    int i = blockIdx.x * blockDim.x + threadIdx.x;
    if (i >= n4) return;
    float4 v = reinterpret_cast<const float4*>(src)[i];
    float4 h, l;
    h.x = tf32_rna(v.x); l.x = tf32_rna(v.x - h.x);
    h.y = tf32_rna(v.y); l.y = tf32_rna(v.y - h.y);
    h.z = tf32_rna(v.z); l.z = tf32_rna(v.z - h.z);
    h.w = tf32_rna(v.w); l.w = tf32_rna(v.w - h.w);
    reinterpret_cast<float4*>(hi)[i] = h;
    reinterpret_cast<float4*>(lo)[i] = l;
}

__global__ void init_count_kernel() {
    if (threadIdx.x == 0) g_count = 0;
}

// ---------------------------------------------------------------------------
// Phase 1: tf32x3 GEMM. CTA 128x128, 8 warps (4m x 2n), warp tile 32x64,
// BK=64, 2-stage cp.async pipeline. A loaded raw, split in registers.
// ---------------------------------------------------------------------------
__global__ __launch_bounds__(256, 1)
void gemm_tf32_kernel(const float* __restrict__ x, const float* __restrict__ bias) {
    extern __shared__ float smf[];
    const uint32_t sbase = smem_u32(smf);

    const int tid = (int)threadIdx.x;
    const int wid = tid >> 5;
    const int lane = tid & 31;
    const int l4 = lane >> 2;
    const int lk = lane & 3;
    const int warp_m = wid >> 1;   // 0..3
    const int warp_n = wid & 1;    // 0..1
    const int bn = blockIdx.x * BN;
    const int bm = blockIdx.y * BM;

    float acc[2][8][4];
#pragma unroll
    for (int mf = 0; mf < 2; mf++)
#pragma unroll
        for (int nf = 0; nf < 8; nf++)
#pragma unroll
            for (int q = 0; q < 4; q++) acc[mf][nf][q] = 0.0f;

    auto fill = [&](int s, int c) {
        const uint32_t st = sbase + (uint32_t)(s * STAGE_W) * 4u;
        const uint32_t uBhi = st + (uint32_t)TILE_W * 4u;
        const uint32_t uBlo = st + (uint32_t)(2 * TILE_W) * 4u;
        const int kbase = c * BK;
        // A raw: 128 rows x 16 granules of 16B
#pragma unroll
        for (int i = tid; i < 2048; i += 256) {
            const int r = i >> 4, q = i & 15;
            const uint32_t doff = (uint32_t)(r * LDK + q * 4) * 4u;
            cp16(st + doff, x + (size_t)(bm + r) * K_TOT + kbase + q * 4);
        }
        // B hi/lo: 2 arrays x 128 rows x 16 granules
#pragma unroll
        for (int i = tid; i < 4096; i += 256) {
            const int arr = i >> 11, rem = i & 2047;
            const int r = rem >> 4, q = rem & 15;
            const uint32_t doff = (uint32_t)(r * LDK + q * 4) * 4u;
            const float* wsrc = arr ? g_wlo : g_whi;
            cp16((arr ? uBlo : uBhi) + doff,
                 wsrc + (size_t)(bn + r) * K_TOT + kbase + q * 4);
        }
    };

    auto compute = [&](int s) {
        const float* As = smf + s * STAGE_W;          // raw A
        const float* Bs_hi = As + TILE_W;
        const float* Bs_lo = As + 2 * TILE_W;
        const int arow = warp_m * 32 + l4;
        const int nrow = warp_n * 64 + l4;
#pragma unroll
        for (int k8 = 0; k8 < BK / 8; k8++) {
            const int ko = k8 * 8 + lk;
            float ah[2][4], al[2][4];
#pragma unroll
            for (int mf = 0; mf < 2; mf++) {
                const int r0 = (arow + mf * 16) * LDK + ko;
                float a0 = As[r0];
                float a1 = As[r0 + 8 * LDK];
                float a2 = As[r0 + 4];
                float a3 = As[r0 + 8 * LDK + 4];
                ah[mf][0] = tf32_rna(a0); al[mf][0] = tf32_rna(a0 - ah[mf][0]);
                ah[mf][1] = tf32_rna(a1); al[mf][1] = tf32_rna(a1 - ah[mf][1]);
                ah[mf][2] = tf32_rna(a2); al[mf][2] = tf32_rna(a2 - ah[mf][2]);
                ah[mf][3] = tf32_rna(a3); al[mf][3] = tf32_rna(a3 - ah[mf][3]);
            }
            float bh[8][2], bl[8][2];
#pragma unroll
            for (int nf = 0; nf < 8; nf++) {
                const int n0 = (nrow + nf * 8) * LDK + ko;
                bh[nf][0] = Bs_hi[n0];
                bh[nf][1] = Bs_hi[n0 + 4];
                bl[nf][0] = Bs_lo[n0];
                bl[nf][1] = Bs_lo[n0 + 4];
            }
#pragma unroll
            for (int mf = 0; mf < 2; mf++)
#pragma unroll
                for (int nf = 0; nf < 8; nf++) {
                    mma_tf32(acc[mf][nf], ah[mf], bh[nf]);
                    mma_tf32(acc[mf][nf], ah[mf], bl[nf]);
                    mma_tf32(acc[mf][nf], al[mf], bh[nf]);
                }
        }
    };

    // 2-stage pipeline, 8 chunks
    fill(0, 0);
    CP_COMMIT();
    fill(1, 1);
    CP_COMMIT();
    for (int c = 0; c < NCHUNK; c++) {
        if (c + 2 <= NCHUNK) { CP_WAIT1(); } else { CP_WAIT0(); }
        __syncthreads();
        compute(c & 1);
        if (c + 2 < NCHUNK) {
            __syncthreads();           // stage (c&1) fully consumed before refill
            fill(c & 1, c + 2);
            CP_COMMIT();
        }
    }

    // Epilogue: + bias -> g_h
#pragma unroll
    for (int nf = 0; nf < 8; nf++) {
        const int col = bn + warp_n * 64 + nf * 8 + lk * 2;
        const float b0 = __ldg(bias + col);
        const float b1 = __ldg(bias + col + 1);
#pragma unroll
        for (int mf = 0; mf < 2; mf++) {
            const int row = bm + warp_m * 32 + mf * 16 + l4;
            float2 v0 = make_float2(acc[mf][nf][0] + b0, acc[mf][nf][1] + b1);
            float2 v1 = make_float2(acc[mf][nf][2] + b0, acc[mf][nf][3] + b1);
            *reinterpret_cast<float2*>(g_h + (size_t)row * N_TOT + col) = v0;
            *reinterpret_cast<float2*>(g_h + (size_t)(row + 8) * N_TOT + col) = v1;
        }
    }
}

// ---------------------------------------------------------------------------
// Phase 2: LIF scan + near-threshold flagging.
// ---------------------------------------------------------------------------
__global__ __launch_bounds__(256)
void lif_scan_flag_kernel(float* __restrict__ out) {
    const int idx = blockIdx.x * 256 + (int)threadIdx.x;
    const float* hp = g_h + idx;
    float* op = out + idx;
    float v = 0.0f;
    bool flag = false;

#pragma unroll 1
    for (int t = 0; t < T_STEPS; t += 16) {
        float h[16];
#pragma unroll
        for (int k = 0; k < 16; k++) h[k] = __ldcg(hp + (size_t)k * BH);
        float sp[16];
#pragma unroll
        for (int k = 0; k < 16; k++) {
            v = fmaf(0.5f, v, h[k]);
            flag = flag || (fabsf(v - 1.0f) < MARGIN);
            const bool f = (v >= 1.0f);
            sp[k] = f ? 1.0f : 0.0f;
            v = f ? 0.0f : v;
        }
#pragma unroll
        for (int k = 0; k < 16; k++) __stcg(op + (size_t)k * BH, sp[k]);
        hp += (size_t)16 * BH;
        op += (size_t)16 * BH;
    }

    if (flag) {
        int p = atomicAdd(&g_count, 1);
        g_list[p] = idx;
    }
}

// ---------------------------------------------------------------------------
// Phase 3: exact fix-up of flagged neurons (bit-exact sequential fp32 chain).
// ---------------------------------------------------------------------------
__global__ __launch_bounds__(256)
void fixup_kernel(const float* __restrict__ x, const float* __restrict__ W,
                  const float* __restrict__ bias, float* __restrict__ out) {
    __shared__ float sW[K_TOT];
    __shared__ float sh[T_STEPS];

    for (int i = blockIdx.x; i < g_count; i += gridDim.x) {
        const int idx = g_list[i];
        const int b = idx >> 9;
        const int hid = idx & 511;

        for (int k = threadIdx.x; k < K_TOT; k += 256)
            sW[k] = W[(size_t)hid * K_TOT + k];
        __syncthreads();

        const int t = (int)threadIdx.x;
        const float4* xr = reinterpret_cast<const float4*>(
            x + ((size_t)t * 128 + b) * K_TOT);
        float acc = 0.0f;
#pragma unroll 4
        for (int k4 = 0; k4 < K_TOT / 4; k4++) {
            const float4 xx = __ldg(xr + k4);
            acc = fmaf(xx.x, sW[k4 * 4 + 0], acc);
            acc = fmaf(xx.y, sW[k4 * 4 + 1], acc);
            acc = fmaf(xx.z, sW[k4 * 4 + 2], acc);
            acc = fmaf(xx.w, sW[k4 * 4 + 3], acc);
        }
        sh[t] = acc + __ldg(bias + hid);
        __syncthreads();

        if (threadIdx.x == 0) {
            float v = 0.0f;
#pragma unroll 1
            for (int t2 = 0; t2 < T_STEPS; t2++) {
                v = fmaf(0.5f, v, sh[t2]);
                const bool f = (v >= 1.0f);
                out[(size_t)t2 * BH + idx] = f ? 1.0f : 0.0f;
                v = f ? 0.0f : v;
            }
        }
        __syncthreads();
    }
}

// ---------------------------------------------------------------------------
extern "C" void kernel_launch(void* const* d_in, const int* in_sizes, int n_in,
                              void* d_out, int out_size) {
    const float* x = (const float*)d_in[0];   // (256,128,512)
    const float* W = (const float*)d_in[1];   // (512,512)
    const float* b = (const float*)d_in[2];   // (512,)
    float* out = (float*)d_out;               // (256,128,512)

    float *whi, *wlo;
    cudaGetSymbolAddress((void**)&whi, g_whi);
    cudaGetSymbolAddress((void**)&wlo, g_wlo);

    cudaFuncSetAttribute(gemm_tf32_kernel,
                         cudaFuncAttributeMaxDynamicSharedMemorySize, SMEM_DYN);

    const int n4w = N_TOT * K_TOT / 4;
    split_kernel<<<(n4w + 255) / 256, 256>>>(W, whi, wlo, n4w);
    init_count_kernel<<<1, 32>>>();

    dim3 grid(N_TOT / BN, M_TOT / BM);  // (4, 256)
    gemm_tf32_kernel<<<grid, 256, SMEM_DYN>>>(x, b);

    lif_scan_flag_kernel<<<BH / 256, 256>>>(out);

    fixup_kernel<<<256, 256>>>(x, W, b, out);
}

// round 17
// speedup vs baseline: 1.4684x; 1.0317x over previous
#include <cuda_runtime.h>
#include <cstdint>

// LIF spiking layer: h = x @ W^T + b (M=32768, N=512, K=512), LIF scan over T.
//
// R16 == R15 resubmission (round-15 bench died to container infra before
// executing): tf32x3 HMMA GEMM (hihi+hilo+lohi), on-the-fly A split, BK=32,
// 2-stage cp.async pipeline at 108 KB smem -> 2 CTAs/SM (occ 2 hides the
// barrier/fill bubbles and the wave tail that capped tensor util at 65%).
// Registers forced <=128 via launch_bounds(256,2); B frags streamed 2 words
// at a time to shrink live state. Flag margin 3e-5 + bit-exact sequential
// fp32 fixup of near-threshold neurons (validated: rel_err 0.0).

#define M_TOT 32768
#define N_TOT 512
#define K_TOT 512
#define T_STEPS 256
#define BH 65536
#define MARGIN 3e-5f

#define BM 128
#define BN 128
#define BK 32
#define NCHUNK (K_TOT / BK)          // 16
#define LDK 36
#define TILE_W (128 * LDK)           // 4608 words = 18432 B
#define STAGE_W (3 * TILE_W)         // 13824 words = 55296 B
#define NSTAGE 2
#define SMEM_DYN (NSTAGE * STAGE_W * 4)   // 110592 B -> 2 CTAs/SM

// Scratch (device globals; allocation forbidden)
__device__ float g_h[M_TOT * N_TOT];    // 64 MB
__device__ float g_whi[N_TOT * K_TOT];  // 1 MB
__device__ float g_wlo[N_TOT * K_TOT];  // 1 MB
__device__ int g_list[BH];
__device__ int g_count;

// ---------------------------------------------------------------------------
__device__ __forceinline__ uint32_t smem_u32(const void* p) {
    uint32_t a;
    asm("{ .reg .u64 t; cvta.to.shared.u64 t, %1; cvt.u32.u64 %0, t; }"
        : "=r"(a) : "l"(p));
    return a;
}
__device__ __forceinline__ void cp16(uint32_t s, const void* g) {
    asm volatile("cp.async.cg.shared.global [%0], [%1], 16;" :: "r"(s), "l"(g));
}
#define CP_COMMIT() asm volatile("cp.async.commit_group;" ::: "memory")
#define CP_WAIT1() asm volatile("cp.async.wait_group 1;" ::: "memory")
#define CP_WAIT0() asm volatile("cp.async.wait_group 0;" ::: "memory")

__device__ __forceinline__ void mma_tf32(float* d, const float* a,
                                         float b0, float b1) {
    asm volatile(
        "mma.sync.aligned.m16n8k8.row.col.f32.tf32.tf32.f32 "
        "{%0,%1,%2,%3}, {%4,%5,%6,%7}, {%8,%9}, {%0,%1,%2,%3};"
        : "+f"(d[0]), "+f"(d[1]), "+f"(d[2]), "+f"(d[3])
        : "r"(__float_as_uint(a[0])), "r"(__float_as_uint(a[1])),
          "r"(__float_as_uint(a[2])), "r"(__float_as_uint(a[3])),
          "r"(__float_as_uint(b0)), "r"(__float_as_uint(b1)));
}
__device__ __forceinline__ float tf32_rna(float x) {
    uint32_t u;
    asm("cvt.rna.tf32.f32 %0, %1;" : "=r"(u) : "f"(x));
    return __uint_as_float(u);
}

// ---------------------------------------------------------------------------
// Phase 0: split W -> (tf32 hi, tf32 lo). Tiny (1 MB).
// ---------------------------------------------------------------------------
__global__ __launch_bounds__(256)
void split_kernel(const float* __restrict__ src, float* __restrict__ hi,
                  float* __restrict__ lo, int n4) {
    int i = blockIdx.x * blockDim.x + threadIdx.x;
    if (i >= n4) return;
    float4 v = reinterpret_cast<const float4*>(src)[i];
    float4 h, l;
    h.x = tf32_rna(v.x); l.x = tf32_rna(v.x - h.x);
    h.y = tf32_rna(v.y); l.y = tf32_rna(v.y - h.y);
    h.z = tf32_rna(v.z); l.z = tf32_rna(v.z - h.z);
    h.w = tf32_rna(v.w); l.w = tf32_rna(v.w - h.w);
    reinterpret_cast<float4*>(hi)[i] = h;
    reinterpret_cast<float4*>(lo)[i] = l;
}

__global__ void init_count_kernel() {
    if (threadIdx.x == 0) g_count = 0;
}

// ---------------------------------------------------------------------------
// Phase 1: tf32x3 GEMM. CTA 128x128, 8 warps (4m x 2n), warp tile 32x64,
// BK=32, 2-stage pipeline, 2 CTAs/SM. A raw in smem, split in registers.
// ---------------------------------------------------------------------------
__global__ __launch_bounds__(256, 2)
void gemm_tf32_kernel(const float* __restrict__ x, const float* __restrict__ bias) {
    extern __shared__ float smf[];
    const uint32_t sbase = smem_u32(smf);

    const int tid = (int)threadIdx.x;
    const int wid = tid >> 5;
    const int lane = tid & 31;
    const int l4 = lane >> 2;
    const int lk = lane & 3;
    const int warp_m = wid >> 1;   // 0..3
    const int warp_n = wid & 1;    // 0..1
    const int bn = blockIdx.x * BN;
    const int bm = blockIdx.y * BM;

    float acc[2][8][4];
#pragma unroll
    for (int mf = 0; mf < 2; mf++)
#pragma unroll
        for (int nf = 0; nf < 8; nf++)
#pragma unroll
            for (int q = 0; q < 4; q++) acc[mf][nf][q] = 0.0f;

    auto fill = [&](int s, int c) {
        const uint32_t st = sbase + (uint32_t)(s * STAGE_W) * 4u;
        const uint32_t uBhi = st + (uint32_t)TILE_W * 4u;
        const uint32_t uBlo = st + (uint32_t)(2 * TILE_W) * 4u;
        const int kbase = c * BK;
        // A raw: 128 rows x 8 granules of 16B
#pragma unroll
        for (int i = tid; i < 1024; i += 256) {
            const int r = i >> 3, q = i & 7;
            const uint32_t doff = (uint32_t)(r * LDK + q * 4) * 4u;
            cp16(st + doff, x + (size_t)(bm + r) * K_TOT + kbase + q * 4);
        }
        // B hi/lo: 2 arrays x 128 rows x 8 granules
#pragma unroll
        for (int i = tid; i < 2048; i += 256) {
            const int arr = i >> 10, rem = i & 1023;
            const int r = rem >> 3, q = rem & 7;
            const uint32_t doff = (uint32_t)(r * LDK + q * 4) * 4u;
            const float* wsrc = arr ? g_wlo : g_whi;
            cp16((arr ? uBlo : uBhi) + doff,
                 wsrc + (size_t)(bn + r) * K_TOT + kbase + q * 4);
        }
    };

    auto compute = [&](int s) {
        const float* As = smf + s * STAGE_W;          // raw A
        const float* Bs_hi = As + TILE_W;
        const float* Bs_lo = As + 2 * TILE_W;
        const int arow = warp_m * 32 + l4;
        const int nrow = warp_n * 64 + l4;
#pragma unroll
        for (int k8 = 0; k8 < BK / 8; k8++) {
            const int ko = k8 * 8 + lk;
            float ah[2][4], al[2][4];
#pragma unroll
            for (int mf = 0; mf < 2; mf++) {
                const int r0 = (arow + mf * 16) * LDK + ko;
                float a0 = As[r0];
                float a1 = As[r0 + 8 * LDK];
                float a2 = As[r0 + 4];
                float a3 = As[r0 + 8 * LDK + 4];
                ah[mf][0] = tf32_rna(a0); al[mf][0] = tf32_rna(a0 - ah[mf][0]);
                ah[mf][1] = tf32_rna(a1); al[mf][1] = tf32_rna(a1 - ah[mf][1]);
                ah[mf][2] = tf32_rna(a2); al[mf][2] = tf32_rna(a2 - ah[mf][2]);
                ah[mf][3] = tf32_rna(a3); al[mf][3] = tf32_rna(a3 - ah[mf][3]);
            }
            // Stream B two words at a time (keeps live regs low for occ 2)
#pragma unroll
            for (int nf = 0; nf < 8; nf++) {
                const int n0 = (nrow + nf * 8) * LDK + ko;
                const float bh0 = Bs_hi[n0];
                const float bh1 = Bs_hi[n0 + 4];
                mma_tf32(acc[0][nf], ah[0], bh0, bh1);
                mma_tf32(acc[1][nf], ah[1], bh0, bh1);
                mma_tf32(acc[0][nf], al[0], bh0, bh1);
                mma_tf32(acc[1][nf], al[1], bh0, bh1);
                const float bl0 = Bs_lo[n0];
                const float bl1 = Bs_lo[n0 + 4];
                mma_tf32(acc[0][nf], ah[0], bl0, bl1);
                mma_tf32(acc[1][nf], ah[1], bl0, bl1);
            }
        }
    };

    // 2-stage pipeline, 16 chunks
    fill(0, 0);
    CP_COMMIT();
    fill(1, 1);
    CP_COMMIT();
    for (int c = 0; c < NCHUNK; c++) {
        if (c + 2 <= NCHUNK) { CP_WAIT1(); } else { CP_WAIT0(); }
        __syncthreads();
        compute(c & 1);
        if (c + 2 < NCHUNK) {
            __syncthreads();           // stage (c&1) fully consumed before refill
            fill(c & 1, c + 2);
            CP_COMMIT();
        }
    }

    // Epilogue: + bias -> g_h
#pragma unroll
    for (int nf = 0; nf < 8; nf++) {
        const int col = bn + warp_n * 64 + nf * 8 + lk * 2;
        const float b0 = __ldg(bias + col);
        const float b1 = __ldg(bias + col + 1);
#pragma unroll
        for (int mf = 0; mf < 2; mf++) {
            const int row = bm + warp_m * 32 + mf * 16 + l4;
            float2 v0 = make_float2(acc[mf][nf][0] + b0, acc[mf][nf][1] + b1);
            float2 v1 = make_float2(acc[mf][nf][2] + b0, acc[mf][nf][3] + b1);
            *reinterpret_cast<float2*>(g_h + (size_t)row * N_TOT + col) = v0;
            *reinterpret_cast<float2*>(g_h + (size_t)(row + 8) * N_TOT + col) = v1;
        }
    }
}

// ---------------------------------------------------------------------------
// Phase 2: LIF scan + near-threshold flagging.
// ---------------------------------------------------------------------------
__global__ __launch_bounds__(256)
void lif_scan_flag_kernel(float* __restrict__ out) {
    const int idx = blockIdx.x * 256 + (int)threadIdx.x;
    const float* hp = g_h + idx;
    float* op = out + idx;
    float v = 0.0f;
    bool flag = false;

#pragma unroll 1
    for (int t = 0; t < T_STEPS; t += 16) {
        float h[16];
#pragma unroll
        for (int k = 0; k < 16; k++) h[k] = __ldcg(hp + (size_t)k * BH);
        float sp[16];
#pragma unroll
        for (int k = 0; k < 16; k++) {
            v = fmaf(0.5f, v, h[k]);
            flag = flag || (fabsf(v - 1.0f) < MARGIN);
            const bool f = (v >= 1.0f);
            sp[k] = f ? 1.0f : 0.0f;
            v = f ? 0.0f : v;
        }
#pragma unroll
        for (int k = 0; k < 16; k++) __stcg(op + (size_t)k * BH, sp[k]);
        hp += (size_t)16 * BH;
        op += (size_t)16 * BH;
    }

    if (flag) {
        int p = atomicAdd(&g_count, 1);
        g_list[p] = idx;
    }
}

// ---------------------------------------------------------------------------
// Phase 3: exact fix-up of flagged neurons (bit-exact sequential fp32 chain).
// ---------------------------------------------------------------------------
__global__ __launch_bounds__(256)
void fixup_kernel(const float* __restrict__ x, const float* __restrict__ W,
                  const float* __restrict__ bias, float* __restrict__ out) {
    __shared__ float sW[K_TOT];
    __shared__ float sh[T_STEPS];

    for (int i = blockIdx.x; i < g_count; i += gridDim.x) {
        const int idx = g_list[i];
        const int b = idx >> 9;
        const int hid = idx & 511;

        for (int k = threadIdx.x; k < K_TOT; k += 256)
            sW[k] = W[(size_t)hid * K_TOT + k];
        __syncthreads();

        const int t = (int)threadIdx.x;
        const float4* xr = reinterpret_cast<const float4*>(
            x + ((size_t)t * 128 + b) * K_TOT);
        float acc = 0.0f;
#pragma unroll 4
        for (int k4 = 0; k4 < K_TOT / 4; k4++) {
            const float4 xx = __ldg(xr + k4);
            acc = fmaf(xx.x, sW[k4 * 4 + 0], acc);
            acc = fmaf(xx.y, sW[k4 * 4 + 1], acc);
            acc = fmaf(xx.z, sW[k4 * 4 + 2], acc);
            acc = fmaf(xx.w, sW[k4 * 4 + 3], acc);
        }
        sh[t] = acc + __ldg(bias + hid);
        __syncthreads();

        if (threadIdx.x == 0) {
            float v = 0.0f;
#pragma unroll 1
            for (int t2 = 0; t2 < T_STEPS; t2++) {
                v = fmaf(0.5f, v, sh[t2]);
                const bool f = (v >= 1.0f);
                out[(size_t)t2 * BH + idx] = f ? 1.0f : 0.0f;
                v = f ? 0.0f : v;
            }
        }
        __syncthreads();
    }
}

// ---------------------------------------------------------------------------
extern "C" void kernel_launch(void* const* d_in, const int* in_sizes, int n_in,
                              void* d_out, int out_size) {
    const float* x = (const float*)d_in[0];   // (256,128,512)
    const float* W = (const float*)d_in[1];   // (512,512)
    const float* b = (const float*)d_in[2];   // (512,)
    float* out = (float*)d_out;               // (256,128,512)

    float *whi, *wlo;
    cudaGetSymbolAddress((void**)&whi, g_whi);
    cudaGetSymbolAddress((void**)&wlo, g_wlo);

    cudaFuncSetAttribute(gemm_tf32_kernel,
                         cudaFuncAttributeMaxDynamicSharedMemorySize, SMEM_DYN);

    const int n4w = N_TOT * K_TOT / 4;
    split_kernel<<<(n4w + 255) / 256, 256>>>(W, whi, wlo, n4w);
    init_count_kernel<<<1, 32>>>();

    dim3 grid(N_TOT / BN, M_TOT / BM);  // (4, 256)
    gemm_tf32_kernel<<<grid, 256, SMEM_DYN>>>(x, b);

    lif_scan_flag_kernel<<<BH / 256, 256>>>(out);

    fixup_kernel<<<256, 256>>>(x, W, b, out);
}